// round 9
// baseline (speedup 1.0000x reference)
#include <cuda_runtime.h>

// NNSystem_mech RHS, one warp, one launch.
// Half-warp branch split (lanes 0-15 ACTH, 16-31 cortisol) — proven R7:
// kernel dur 5.06 -> 4.54us. redux.sync.add.f32 is NOT supported on sm_103
// (ptxas rejects; R8), so reduction stays on SHFL — but shortened:
// lane j<5 of each half folds hidden units j and j+5 locally (independent
// softplus chains pipeline through MUFU), leaving 5 partials -> 3-step
// butterfly (offsets 4,2,1) instead of 4 steps. Chain -26cyc, SHFL issues 8->6.

__device__ __forceinline__ float sp(float x) {
    // direct softplus: all pre-activations here are O(1); no overflow risk.
    return __logf(1.0f + __expf(x));
}

__global__ void __launch_bounds__(32, 1) nnsys_kernel(
    const float* __restrict__ y,
    const float* __restrict__ aiw, const float* __restrict__ aib,
    const float* __restrict__ apw1, const float* __restrict__ apb1,
    const float* __restrict__ apw2, const float* __restrict__ apb2,
    const float* __restrict__ anw1, const float* __restrict__ anb1,
    const float* __restrict__ anw2, const float* __restrict__ anb2,
    const float* __restrict__ arw,  const float* __restrict__ arb,
    const float* __restrict__ ciw,  const float* __restrict__ cib,
    const float* __restrict__ cpw1, const float* __restrict__ cpb1,
    const float* __restrict__ cpw2, const float* __restrict__ cpb2,
    const float* __restrict__ cnw1, const float* __restrict__ cnb1,
    const float* __restrict__ cnw2, const float* __restrict__ cnb2,
    const float* __restrict__ crw,  const float* __restrict__ crb,
    const float* __restrict__ K_i,  const float* __restrict__ n_hill,
    float* __restrict__ out)
{
    const int lane  = threadIdx.x;
    const int j     = lane & 15;         // index within half
    const bool cort = lane >= 16;        // which branch this half computes

    // ---- per-half operand selection (SEL pairs, off the critical path) ----
    const float* iw  = cort ? ciw  : aiw;
    const float* ib  = cort ? cib  : aib;
    const float* pw1 = cort ? cpw1 : apw1;
    const float* pb1 = cort ? cpb1 : apb1;
    const float* pw2 = cort ? cpw2 : apw2;
    const float* nw1 = cort ? cnw1 : anw1;
    const float* nb1 = cort ? cnb1 : anb1;
    const float* nw2 = cort ? cnw2 : anw2;

    // ---- front-batched loads ----
    const float2 yv = *reinterpret_cast<const float2*>(y);   // y0, y1
    const float yin = cort ? yv.y : yv.x;

    const float pb2 = cort ? cpb2[0] : apb2[0];
    const float nb2 = cort ? cnb2[0] : anb2[0];
    const float rw0 = cort ? crw[0]  : arw[0];
    const float rw1 = cort ? crw[1]  : arw[1];
    const float rb  = cort ? crb[0]  : arb[0];
    const float Kv  = K_i[0], nH = n_hill[0];

    // ---- initial 1->2 linear + softplus (per half; independent chains) ----
    const float h0 = sp(fmaf(iw[0], yin, ib[0]));
    const float h1 = sp(fmaf(iw[1], yin, ib[1]));

    // ---- tiny MLPs: lane j<5 folds hidden units j and j+5 of each MLP.
    //      The two softplus evaluations per value are independent -> pipeline.
    float pp = 0.0f, nn = 0.0f;
    if (j < 5) {
        const int k = j + 5;
        pp = fmaf(pw2[j], sp(fmaf(pw1[j], h0, pb1[j])),
                  pw2[k] * sp(fmaf(pw1[k], h0, pb1[k])));
        nn = fmaf(nw2[j], sp(fmaf(nw1[j], h1, nb1[j])),
                  nw2[k] * sp(fmaf(nw1[k], h1, nb1[k])));
    }

    // ---- Hill term (only lane 0 consumes it; computed everywhere so its
    //      MUFU chain overlaps the butterfly). K=1.5>0, y1 in (0,1). ----
    const float Kn   = __powf(Kv, nH);
    const float hill = __fdividef(Kn, Kn + __powf(yv.y, nH));

    // ---- 3-step butterfly per half: partials live in lanes {0..4} (+16);
    //      offsets 4/2/1 mix only within each 8-lane group, lanes 5-7 zero,
    //      so lane 0 / lane 16 end with the exact 10-unit sums. ----
    #pragma unroll
    for (int ofs = 4; ofs > 0; ofs >>= 1) {
        pp += __shfl_xor_sync(0xFFFFFFFFu, pp, ofs);
        nn += __shfl_xor_sync(0xFFFFFFFFu, nn, ofs);
    }

    // ---- epilogue: lane 0 (ACTH) and lane 16 (cortisol) concurrently ----
    if (j == 0) {
        const float gate   = cort ? yv.x : hill;     // y0 * c_pos vs hill * a_pos
        const float pos_in = gate * (pp + pb2);
        const float neg_in = nn + nb2;
        out[(int)cort] = fmaf(rw0, sp(pos_in), fmaf(rw1, sp(neg_in), rb));
    }
}

extern "C" void kernel_launch(void* const* d_in, const int* in_sizes, int n_in,
                              void* d_out, int out_size) {
    // metadata order mirrors reference() signature:
    //  0:t 1:y 2:aiw 3:aib 4:apw1 5:apb1 6:apw2 7:apb2
    //  8:anw1 9:anb1 10:anw2 11:anb2 12:arw 13:arb
    // 14:ciw 15:cib 16:cpw1 17:cpb1 18:cpw2 19:cpb2
    // 20:cnw1 21:cnb1 22:cnw2 23:cnb2 24:crw 25:crb 26:K_i 27:n_hill
    nnsys_kernel<<<1, 32>>>(
        (const float*)d_in[1],
        (const float*)d_in[2],  (const float*)d_in[3],
        (const float*)d_in[4],  (const float*)d_in[5],
        (const float*)d_in[6],  (const float*)d_in[7],
        (const float*)d_in[8],  (const float*)d_in[9],
        (const float*)d_in[10], (const float*)d_in[11],
        (const float*)d_in[12], (const float*)d_in[13],
        (const float*)d_in[14], (const float*)d_in[15],
        (const float*)d_in[16], (const float*)d_in[17],
        (const float*)d_in[18], (const float*)d_in[19],
        (const float*)d_in[20], (const float*)d_in[21],
        (const float*)d_in[22], (const float*)d_in[23],
        (const float*)d_in[24], (const float*)d_in[25],
        (const float*)d_in[26], (const float*)d_in[27],
        (float*)d_out);
}

// round 10
// speedup vs baseline: 1.0287x; 1.0287x over previous
#include <cuda_runtime.h>

// NNSystem_mech RHS, one warp, one launch.
// Proven structure (R7): half-warp branch split — lanes 0-15 ACTH, 16-31
// cortisol, 1 hidden unit per lane, 4-step SHFL butterfly per half.
// R8's 2-unit fold REGRESSED (4.54->4.80us kernel dur): extra MUFU issue +
// FMA on the summing lane outweighed one removed SHFL step. Reverted.
// R9 change: branchless everywhere. ptxas turns multi-instruction if{} arms
// into BSSY/BSYNC (~33-56cyc each). Two such arms existed:
//   - MLP block (j<10): now unconditional with min(j,9) clamp + FSEL zero.
//   - epilogue (j==0): butterfly leaves the sum in EVERY lane, so all lanes
//     compute the epilogue; only the STG is guarded (1-instr arm -> @P STG).

__device__ __forceinline__ float sp(float x) {
    // direct softplus: all pre-activations here are O(1); no overflow risk.
    return __logf(1.0f + __expf(x));
}

__global__ void __launch_bounds__(32, 1) nnsys_kernel(
    const float* __restrict__ y,
    const float* __restrict__ aiw, const float* __restrict__ aib,
    const float* __restrict__ apw1, const float* __restrict__ apb1,
    const float* __restrict__ apw2, const float* __restrict__ apb2,
    const float* __restrict__ anw1, const float* __restrict__ anb1,
    const float* __restrict__ anw2, const float* __restrict__ anb2,
    const float* __restrict__ arw,  const float* __restrict__ arb,
    const float* __restrict__ ciw,  const float* __restrict__ cib,
    const float* __restrict__ cpw1, const float* __restrict__ cpb1,
    const float* __restrict__ cpw2, const float* __restrict__ cpb2,
    const float* __restrict__ cnw1, const float* __restrict__ cnb1,
    const float* __restrict__ cnw2, const float* __restrict__ cnb2,
    const float* __restrict__ crw,  const float* __restrict__ crb,
    const float* __restrict__ K_i,  const float* __restrict__ n_hill,
    float* __restrict__ out)
{
    const int lane  = threadIdx.x;
    const int j     = lane & 15;         // index within half
    const bool cort = lane >= 16;        // which branch this half computes

    // ---- per-half operand selection (SEL pairs, off the critical path) ----
    const float* iw  = cort ? ciw  : aiw;
    const float* ib  = cort ? cib  : aib;
    const float* pw1 = cort ? cpw1 : apw1;
    const float* pb1 = cort ? cpb1 : apb1;
    const float* pw2 = cort ? cpw2 : apw2;
    const float* nw1 = cort ? cnw1 : anw1;
    const float* nb1 = cort ? cnb1 : anb1;
    const float* nw2 = cort ? cnw2 : anw2;

    // ---- front-batched loads ----
    const float2 yv = *reinterpret_cast<const float2*>(y);   // y0, y1
    const float yin = cort ? yv.y : yv.x;

    const float pb2 = cort ? cpb2[0] : apb2[0];
    const float nb2 = cort ? cnb2[0] : anb2[0];
    const float rw0 = cort ? crw[0]  : arw[0];
    const float rw1 = cort ? crw[1]  : arw[1];
    const float rb  = cort ? crb[0]  : arb[0];
    const float Kv  = K_i[0], nH = n_hill[0];

    // ---- initial 1->2 linear + softplus (per half; independent chains) ----
    const float h0 = sp(fmaf(iw[0], yin, ib[0]));
    const float h1 = sp(fmaf(iw[1], yin, ib[1]));

    // ---- tiny MLPs, branchless: lane j owns hidden unit min(j,9); lanes
    //      10-15 recompute unit 9 (valid memory, finite values) and are
    //      zeroed by FSEL so the butterfly sums each unit exactly once. ----
    const int  ji   = (j < 10) ? j : 9;       // IMNMX
    const bool live = (j < 10);
    float pp = pw2[ji] * sp(fmaf(pw1[ji], h0, pb1[ji]));
    float nn = nw2[ji] * sp(fmaf(nw1[ji], h1, nb1[ji]));
    pp = live ? pp : 0.0f;                    // FSEL, no branch
    nn = live ? nn : 0.0f;

    // ---- Hill term (computed everywhere; MUFU chain overlaps butterfly).
    //      K=1.5>0, y1 in (0,1): __powf safe. ----
    const float Kn   = __powf(Kv, nH);
    const float hill = __fdividef(Kn, Kn + __powf(yv.y, nH));

    // ---- 4-step butterfly within each 16-lane half: offsets <16 never
    //      cross the half boundary; EVERY lane ends with its half's sums. ----
    #pragma unroll
    for (int ofs = 8; ofs > 0; ofs >>= 1) {
        pp += __shfl_xor_sync(0xFFFFFFFFu, pp, ofs);
        nn += __shfl_xor_sync(0xFFFFFFFFu, nn, ofs);
    }

    // ---- epilogue on ALL lanes (values are uniform per half); only the
    //      store is guarded -> single predicated STG, no BSSY/BSYNC. ----
    const float gate   = cort ? yv.x : hill;   // y0 * c_pos vs hill * a_pos
    const float pos_in = gate * (pp + pb2);
    const float neg_in = nn + nb2;
    const float res = fmaf(rw0, sp(pos_in), fmaf(rw1, sp(neg_in), rb));
    if (j == 0)
        out[(int)cort] = res;
}

extern "C" void kernel_launch(void* const* d_in, const int* in_sizes, int n_in,
                              void* d_out, int out_size) {
    // metadata order mirrors reference() signature:
    //  0:t 1:y 2:aiw 3:aib 4:apw1 5:apb1 6:apw2 7:apb2
    //  8:anw1 9:anb1 10:anw2 11:anb2 12:arw 13:arb
    // 14:ciw 15:cib 16:cpw1 17:cpb1 18:cpw2 19:cpb2
    // 20:cnw1 21:cnb1 22:cnw2 23:cnb2 24:crw 25:crb 26:K_i 27:n_hill
    nnsys_kernel<<<1, 32>>>(
        (const float*)d_in[1],
        (const float*)d_in[2],  (const float*)d_in[3],
        (const float*)d_in[4],  (const float*)d_in[5],
        (const float*)d_in[6],  (const float*)d_in[7],
        (const float*)d_in[8],  (const float*)d_in[9],
        (const float*)d_in[10], (const float*)d_in[11],
        (const float*)d_in[12], (const float*)d_in[13],
        (const float*)d_in[14], (const float*)d_in[15],
        (const float*)d_in[16], (const float*)d_in[17],
        (const float*)d_in[18], (const float*)d_in[19],
        (const float*)d_in[20], (const float*)d_in[21],
        (const float*)d_in[22], (const float*)d_in[23],
        (const float*)d_in[24], (const float*)d_in[25],
        (const float*)d_in[26], (const float*)d_in[27],
        (float*)d_out);
}